// round 9
// baseline (speedup 1.0000x reference)
#include <cuda_runtime.h>
#include <cuda_fp16.h>
#include <cuda_bf16.h>
#include <mma.h>
#include <math.h>

using namespace nvcuda;

#define NN 100000
#define EE 3200000
#define DD 64
constexpr float EPSF = 0.01f;
#define SB ((NN + 255) / 256)   // 391 scan blocks

#define BNT 216   // k1 B/OUT padded col count (208 used = 13 wmma tiles)
#define AP  72    // k1 A tile pitch (fp32)

// ---------------- scratch (device globals; no allocation allowed) ----------------
__device__ __align__(16) float  g_x [NN * DD];   // node state h
__device__ __align__(16) float  g_v [NN * DD];   // velocity (vp after k1)
__device__ __align__(16) __half g_lxh[NN * DD];  // fp16 lx for the gather
__device__ __align__(16) float  g_a  [NN];
__device__ __align__(16) float  g_b  [NN];       // x@wb + rb
__device__ __align__(16) float2 g_ad [NN];       // (a, dinv)
// CSR by col (for agg) and by row (for deg)
__device__ __align__(16) int g_ccnt [NN];
__device__ __align__(16) int g_cptr [NN + 1];
__device__ __align__(16) int g_cfill[NN];
__device__ __align__(16) int g_src  [EE];        // source node per col-CSR slot
__device__ __align__(16) int g_rcnt [NN];
__device__ __align__(16) int g_rptr [NN + 1];
__device__ __align__(16) int g_rfill[NN];
__device__ __align__(16) int g_rcol [EE];        // dest node per row-CSR slot
__device__ __align__(16) int g_cpart[512];
__device__ __align__(16) int g_rpart[512];

// ---------------- CSR build (self-edges dropped: valid = row!=col) ----------------
__global__ void zero_cnt_kernel() {
    int i = blockIdx.x * blockDim.x + threadIdx.x;
    if (i < NN) { g_ccnt[i] = 0; g_rcnt[i] = 0; }
}

__global__ void count_kernel(const int* __restrict__ ei) {
    int e = blockIdx.x * blockDim.x + threadIdx.x;
    if (e >= EE) return;
    int r = ei[e], c = ei[EE + e];
    if (r == c) return;
    atomicAdd(&g_ccnt[c], 1);
    atomicAdd(&g_rcnt[r], 1);
}

// --- multi-block scan: partial sums -> scan partials -> expand ---
__global__ void partial_kernel() {
    __shared__ int smc[256], smr[256];
    int t = threadIdx.x;
    int i = blockIdx.x * 256 + t;
    int vc = (i < NN) ? g_ccnt[i] : 0;
    int vr = (i < NN) ? g_rcnt[i] : 0;
    smc[t] = vc; smr[t] = vr;
    __syncthreads();
#pragma unroll
    for (int off = 128; off; off >>= 1) {
        if (t < off) { smc[t] += smc[t + off]; smr[t] += smr[t + off]; }
        __syncthreads();
    }
    if (t == 0) { g_cpart[blockIdx.x] = smc[0]; g_rpart[blockIdx.x] = smr[0]; }
}

__global__ void scanpart_kernel() {
    __shared__ int smc[512], smr[512];
    int t = threadIdx.x;
    int vc = (t < SB) ? g_cpart[t] : 0;
    int vr = (t < SB) ? g_rpart[t] : 0;
    smc[t] = vc; smr[t] = vr;
    __syncthreads();
#pragma unroll
    for (int off = 1; off < 512; off <<= 1) {
        int ac = (t >= off) ? smc[t - off] : 0;
        int ar = (t >= off) ? smr[t - off] : 0;
        __syncthreads();
        smc[t] += ac; smr[t] += ar;
        __syncthreads();
    }
    if (t < SB) { g_cpart[t] = smc[t] - vc; g_rpart[t] = smr[t] - vr; }
    if (t == 511) { g_cptr[NN] = smc[511]; g_rptr[NN] = smr[511]; }
}

__global__ void expand_kernel() {
    __shared__ int smc[256], smr[256];
    int b = blockIdx.x, t = threadIdx.x;
    int i = b * 256 + t;
    int vc = (i < NN) ? g_ccnt[i] : 0;
    int vr = (i < NN) ? g_rcnt[i] : 0;
    smc[t] = vc; smr[t] = vr;
    __syncthreads();
#pragma unroll
    for (int off = 1; off < 256; off <<= 1) {
        int ac = (t >= off) ? smc[t - off] : 0;
        int ar = (t >= off) ? smr[t - off] : 0;
        __syncthreads();
        smc[t] += ac; smr[t] += ar;
        __syncthreads();
    }
    if (i < NN) {
        int pc = g_cpart[b] + smc[t] - vc;
        int pr = g_rpart[b] + smr[t] - vr;
        g_cptr[i] = pc; g_cfill[i] = pc;
        g_rptr[i] = pr; g_rfill[i] = pr;
    }
}

__global__ void scatter_kernel(const int* __restrict__ ei) {
    int e = blockIdx.x * blockDim.x + threadIdx.x;
    if (e >= EE) return;
    int r = ei[e], c = ei[EE + e];
    if (r == c) return;
    int sc = atomicAdd(&g_cfill[c], 1);
    g_src[sc] = r;
    int sr = atomicAdd(&g_rfill[r], 1);
    g_rcol[sr] = c;
}

// ---------------- shared helpers ----------------
__device__ __forceinline__ void load_xtile(const float* __restrict__ X, float* Xs,
                                           int node0, int nrows, int tid) {
    // Xs[k][m], pitch 68 floats, 64x64 tile transposed
    for (int i = tid; i < 1024; i += 256) {
        int m = i >> 4, q = i & 15;
        float4 v = make_float4(0.f, 0.f, 0.f, 0.f);
        int node = node0 + m;
        if (node < nrows) v = reinterpret_cast<const float4*>(X)[node * 16 + q];
        int k = q * 4;
        Xs[(k + 0) * 68 + m] = v.x;
        Xs[(k + 1) * 68 + m] = v.y;
        Xs[(k + 2) * 68 + m] = v.z;
        Xs[(k + 3) * 68 + m] = v.w;
    }
}

__device__ __forceinline__ float gelu_tanh(float x) {
    float x3 = x * x * x;
    float t = tanhf(0.7978845608028654f * (x + 0.044715f * x3));
    return 0.5f * x * (1.0f + t);
}

// ---------------- generic GEMM: Y[m][0..BN) = X[m] @ W + bias (R4 FFMA) ----------
template <int BN>
__global__ void gemm_kernel(const float* __restrict__ X, const float* __restrict__ W,
                            const float* __restrict__ bias, float* __restrict__ Y,
                            int nrows) {
    __shared__ float Ws[64 * BN];
    __shared__ float Xs[64 * 68];
    int tid = threadIdx.x;
    for (int i = tid; i < 64 * BN / 4; i += 256)
        reinterpret_cast<float4*>(Ws)[i] = reinterpret_cast<const float4*>(W)[i];
    int node0 = blockIdx.x * 64;
    load_xtile(X, Xs, node0, nrows, tid);
    __syncthreads();

    constexpr int NT = BN / 16;
    int tm = tid & 15, tn = tid >> 4;
    int m0 = tm * 4;
    float acc[4][NT];
#pragma unroll
    for (int i = 0; i < 4; ++i)
#pragma unroll
        for (int j = 0; j < NT; ++j) acc[i][j] = 0.f;

#pragma unroll 4
    for (int k = 0; k < 64; ++k) {
        float4 xv = *reinterpret_cast<const float4*>(Xs + k * 68 + m0);
        float xr[4] = {xv.x, xv.y, xv.z, xv.w};
        float wr[NT];
#pragma unroll
        for (int j = 0; j < NT; ++j) wr[j] = Ws[k * BN + tn * NT + j];
#pragma unroll
        for (int i = 0; i < 4; ++i)
#pragma unroll
            for (int j = 0; j < NT; ++j) acc[i][j] = fmaf(xr[i], wr[j], acc[i][j]);
    }
    float br[NT];
#pragma unroll
    for (int j = 0; j < NT; ++j) br[j] = bias[tn * NT + j];
#pragma unroll
    for (int i = 0; i < 4; ++i) {
        int m = node0 + m0 + i;
        if (m < nrows) {
#pragma unroll
            for (int j = 0; j < NT; ++j) Y[m * BN + tn * NT + j] = acc[i][j] + br[j];
        }
    }
}

// ---------------- k1 (wmma 3xTF32): [lin|diss|forc|wa|wb] GEMM + partial v update --
// Split-precision tf32: A = Ah + Al, B = Bh + Bl; OUT = Ah*Bh + Ah*Bl + Al*Bh
// (fp32-equivalent accuracy on the tensor pipe).
// vp = v*(1 - EPS*relu(diss)) - EPS*lx + EPS*forc ; lx stored fp16 for gather;
// a = OUT[:,192], b = OUT[:,193] + rb.
__global__ void k1_kernel(const float* __restrict__ Wl, const float* __restrict__ bl,
                          const float* __restrict__ Wd, const float* __restrict__ bd,
                          const float* __restrict__ Wf, const float* __restrict__ bfv,
                          const float* __restrict__ res_w_blk,
                          const float* __restrict__ res_b_blk) {
    extern __shared__ float smf[];
    float* Ah = smf;                         // 64 x 72
    float* Al = Ah + 64 * AP;                // 64 x 72
    float* Bh = Al + 64 * AP;                // 64 x 216
    float* Bl = Bh + 64 * BNT;               // 64 x 216
    float* Os = Bl + 64 * BNT;               // 64 x 216 fp32 accum
    int tid = threadIdx.x;
    int node0 = blockIdx.x * 64;

    // fill A: x tile split into tf32 hi/lo
    for (int idx = tid; idx < 64 * 64; idx += 256) {
        int m = idx >> 6, k = idx & 63;
        int node = node0 + m;
        float v = (node < NN) ? g_x[node * 64 + k] : 0.f;
        float hi = wmma::__float_to_tf32(v);
        Ah[m * AP + k] = hi;
        Al[m * AP + k] = wmma::__float_to_tf32(v - hi);
    }
    // fill B: [lin | diss | forc | wa wb | 0-pad] split into tf32 hi/lo
    for (int idx = tid; idx < 64 * BNT; idx += 256) {
        int k = idx / BNT, n = idx % BNT;
        float v;
        if (n < 64)       v = Wl[k * 64 + n];
        else if (n < 128) v = Wd[k * 64 + (n - 64)];
        else if (n < 192) v = Wf[k * 64 + (n - 128)];
        else if (n == 192) v = res_w_blk[k];
        else if (n == 193) v = res_w_blk[64 + k];
        else v = 0.f;
        float hi = wmma::__float_to_tf32(v);
        Bh[k * BNT + n] = hi;
        Bl[k * BNT + n] = wmma::__float_to_tf32(v - hi);
    }
    __syncthreads();

    int warp = tid >> 5;
    // 52 jobs: mi = job & 3 (4 M-tiles), nt = job >> 2 (13 N-tiles)
    for (int job = warp; job < 52; job += 8) {
        int mi = job & 3, nt = job >> 2;
        wmma::fragment<wmma::accumulator, 16, 16, 8, float> c;
        wmma::fill_fragment(c, 0.f);
#pragma unroll
        for (int kt = 0; kt < 8; ++kt) {
            wmma::fragment<wmma::matrix_a, 16, 16, 8, wmma::precision::tf32, wmma::row_major> ah, al;
            wmma::fragment<wmma::matrix_b, 16, 16, 8, wmma::precision::tf32, wmma::row_major> bh, bl2;
            wmma::load_matrix_sync(ah, Ah + mi * 16 * AP + kt * 8, AP);
            wmma::load_matrix_sync(al, Al + mi * 16 * AP + kt * 8, AP);
            wmma::load_matrix_sync(bh, Bh + kt * 8 * BNT + nt * 16, BNT);
            wmma::load_matrix_sync(bl2, Bl + kt * 8 * BNT + nt * 16, BNT);
            wmma::mma_sync(c, al, bh, c);
            wmma::mma_sync(c, ah, bl2, c);
            wmma::mma_sync(c, ah, bh, c);
        }
        wmma::store_matrix_sync(Os + mi * 16 * BNT + nt * 16, c, BNT, wmma::mem_row_major);
    }
    __syncthreads();

    // epilogue: vp update + fp16 lx (thread = (m mod 4, j); coalesced in j)
    {
        int j = tid & 63;
        float blj = bl[j], bdj = bd[j], bfj = bfv[j];
        for (int m = tid >> 6; m < 64; m += 4) {
            int node = node0 + m;
            if (node < NN) {
                float lxv = Os[m * BNT + j] + blj;
                float ds  = fmaxf(Os[m * BNT + 64 + j] + bdj, 0.f);
                float fc  = Os[m * BNT + 128 + j] + bfj;
                float vv  = g_v[node * 64 + j];
                float vp  = vv - EPSF * (lxv + ds * vv - fc);
                g_v[node * 64 + j] = vp;
                g_lxh[node * 64 + j] = __float2half(lxv);
            }
        }
    }
    if (tid < 64) {
        int node = node0 + tid;
        if (node < NN) {
            g_a[node] = Os[tid * BNT + 192];
            g_b[node] = Os[tid * BNT + 193] + res_b_blk[0];
        }
    }
}

// ---------------- fused MLP block: h += gelu(h@W1+b1)@W2+b2 (R4 FFMA) -------------
__global__ void mlp_kernel(const float* __restrict__ W1, const float* __restrict__ b1,
                           const float* __restrict__ W2, const float* __restrict__ b2) {
    extern __shared__ float sm[];
    float* W1s = sm;                 // 4096
    float* W2s = sm + 4096;          // 4096
    float* Xs  = sm + 8192;          // 64*68
    float* Ts  = sm + 8192 + 4352;   // 64*68
    int tid = threadIdx.x;
    for (int i = tid; i < 1024; i += 256) {
        reinterpret_cast<float4*>(W1s)[i] = reinterpret_cast<const float4*>(W1)[i];
        reinterpret_cast<float4*>(W2s)[i] = reinterpret_cast<const float4*>(W2)[i];
    }
    int node0 = blockIdx.x * 64;
    load_xtile(g_x, Xs, node0, NN, tid);
    __syncthreads();

    int tm = tid & 15, tn = tid >> 4;
    int m0 = tm * 4;
    float acc[4][4];
#pragma unroll
    for (int i = 0; i < 4; ++i)
#pragma unroll
        for (int j = 0; j < 4; ++j) acc[i][j] = 0.f;

#pragma unroll 4
    for (int k = 0; k < 64; ++k) {
        float4 xv = *reinterpret_cast<const float4*>(Xs + k * 68 + m0);
        float xr[4] = {xv.x, xv.y, xv.z, xv.w};
        float4 wv = *reinterpret_cast<const float4*>(W1s + k * 64 + tn * 4);
        float wr[4] = {wv.x, wv.y, wv.z, wv.w};
#pragma unroll
        for (int i = 0; i < 4; ++i)
#pragma unroll
            for (int j = 0; j < 4; ++j) acc[i][j] = fmaf(xr[i], wr[j], acc[i][j]);
    }
    float4 bb1 = *reinterpret_cast<const float4*>(b1 + tn * 4);
    float br1[4] = {bb1.x, bb1.y, bb1.z, bb1.w};
#pragma unroll
    for (int i = 0; i < 4; ++i)
#pragma unroll
        for (int j = 0; j < 4; ++j)
            Ts[(tn * 4 + j) * 68 + m0 + i] = gelu_tanh(acc[i][j] + br1[j]);
    __syncthreads();

    float acc2[4][4];
#pragma unroll
    for (int i = 0; i < 4; ++i)
#pragma unroll
        for (int j = 0; j < 4; ++j) acc2[i][j] = 0.f;
#pragma unroll 4
    for (int k = 0; k < 64; ++k) {
        float4 tv = *reinterpret_cast<const float4*>(Ts + k * 68 + m0);
        float tr[4] = {tv.x, tv.y, tv.z, tv.w};
        float4 wv = *reinterpret_cast<const float4*>(W2s + k * 64 + tn * 4);
        float wr[4] = {wv.x, wv.y, wv.z, wv.w};
#pragma unroll
        for (int i = 0; i < 4; ++i)
#pragma unroll
            for (int j = 0; j < 4; ++j) acc2[i][j] = fmaf(tr[i], wr[j], acc2[i][j]);
    }
    float4 bb2 = *reinterpret_cast<const float4*>(b2 + tn * 4);
    float br2[4] = {bb2.x, bb2.y, bb2.z, bb2.w};
#pragma unroll
    for (int i = 0; i < 4; ++i) {
        int m = node0 + m0 + i;
        if (m < NN) {
#pragma unroll
            for (int j = 0; j < 4; ++j) {
                int n = tn * 4 + j;
                g_x[m * 64 + n] = Xs[n * 68 + m0 + i] + acc2[i][j] + br2[j];
            }
        }
    }
}

// ---------------- deg via row-CSR gather (no atomics) + dinv fused ----------------
__global__ void deg_kernel() {
    int warp = (blockIdx.x * blockDim.x + threadIdx.x) >> 5;
    int lane = threadIdx.x & 31;
    if (warp >= NN) return;
    int r = warp;
    int lo = g_rptr[r], hi = g_rptr[r + 1];
    float a_r = __ldg(&g_a[r]);
    float s = 0.f;
#pragma unroll 4
    for (int p = lo + lane; p < hi; p += 32) {
        int c = __ldg(&g_rcol[p]);
        float z = a_r + __ldg(&g_b[c]);
        if (z > 0.f) s += z;
    }
#pragma unroll
    for (int off = 16; off; off >>= 1) s += __shfl_xor_sync(0xFFFFFFFFu, s, off);
    if (lane == 0)
        g_ad[r] = make_float2(a_r, (s > 0.f) ? rsqrtf(s) : 0.f);
}

// ---------------- aggregation + v/x update (warp per destination node) ----------------
// R4 version (measured fastest): lane-parallel metadata, 4-wide gather MLP.
__global__ void agg_kernel() {
    int warp = (blockIdx.x * blockDim.x + threadIdx.x) >> 5;
    int lane = threadIdx.x & 31;
    if (warp >= NN) return;
    int c = warp;
    int p = g_cptr[c], end = g_cptr[c + 1];
    float dc = __ldg(&g_ad[c]).y;
    float bc = __ldg(&g_b[c]);
    float acc0 = 0.f, acc1 = 0.f;
    const __half2* lxh2 = reinterpret_cast<const __half2*>(g_lxh);

    for (int base = p; base < end; base += 32) {
        int e = base + lane;
        int s = 0;
        float w = 0.f;
        if (e < end) {
            s = __ldg(&g_src[e]);
            float2 ads = __ldg(&g_ad[s]);
            float z = ads.x + bc;
            w = (z > 0.f) ? z * ads.y : 0.f;
        }
        unsigned mask = __ballot_sync(0xFFFFFFFFu, w > 0.f);
        while (mask) {
            int b0 = __ffs(mask) - 1; mask &= mask - 1;
            int b1 = b0, b2 = b0, b3 = b0;
            bool v1 = false, v2 = false, v3 = false;
            if (mask) { b1 = __ffs(mask) - 1; mask &= mask - 1; v1 = true; }
            if (mask) { b2 = __ffs(mask) - 1; mask &= mask - 1; v2 = true; }
            if (mask) { b3 = __ffs(mask) - 1; mask &= mask - 1; v3 = true; }
            float w0 = __shfl_sync(0xFFFFFFFFu, w, b0);
            float w1 = __shfl_sync(0xFFFFFFFFu, w, b1);
            float w2 = __shfl_sync(0xFFFFFFFFu, w, b2);
            float w3 = __shfl_sync(0xFFFFFFFFu, w, b3);
            int   s0 = __shfl_sync(0xFFFFFFFFu, s, b0);
            int   s1 = __shfl_sync(0xFFFFFFFFu, s, b1);
            int   s2 = __shfl_sync(0xFFFFFFFFu, s, b2);
            int   s3 = __shfl_sync(0xFFFFFFFFu, s, b3);
            if (!v1) w1 = 0.f;
            if (!v2) w2 = 0.f;
            if (!v3) w3 = 0.f;
            __half2 h0 = __ldg(lxh2 + s0 * 32 + lane);
            __half2 h1 = __ldg(lxh2 + s1 * 32 + lane);
            __half2 h2 = __ldg(lxh2 + s2 * 32 + lane);
            __half2 h3 = __ldg(lxh2 + s3 * 32 + lane);
            float2 lf0 = __half22float2(h0);
            float2 lf1 = __half22float2(h1);
            float2 lf2 = __half22float2(h2);
            float2 lf3 = __half22float2(h3);
            acc0 = fmaf(w0, lf0.x, acc0); acc1 = fmaf(w0, lf0.y, acc1);
            acc0 = fmaf(w1, lf1.x, acc0); acc1 = fmaf(w1, lf1.y, acc1);
            acc0 = fmaf(w2, lf2.x, acc0); acc1 = fmaf(w2, lf2.y, acc1);
            acc0 = fmaf(w3, lf3.x, acc0); acc1 = fmaf(w3, lf3.y, acc1);
        }
    }
    int idx = c * 32 + lane;
    float2 vv = reinterpret_cast<float2*>(g_v)[idx];   // vp from k1
    float2 xx = reinterpret_cast<float2*>(g_x)[idx];
    vv.x += EPSF * dc * acc0;
    vv.y += EPSF * dc * acc1;
    xx.x += EPSF * vv.x;
    xx.y += EPSF * vv.y;
    reinterpret_cast<float2*>(g_v)[idx] = vv;
    reinterpret_cast<float2*>(g_x)[idx] = xx;
}

// ---------------- host launch ----------------
extern "C" void kernel_launch(void* const* d_in, const int* in_sizes, int n_in,
                              void* d_out, int out_size) {
    const float* x_in    = (const float*)d_in[0];
    const int*   ei      = (const int*)  d_in[1];
    const float* enc_w   = (const float*)d_in[2];
    const float* enc_b   = (const float*)d_in[3];
    const float* vel_w   = (const float*)d_in[4];
    const float* vel_b   = (const float*)d_in[5];
    const float* res_w   = (const float*)d_in[6];
    const float* res_b   = (const float*)d_in[7];
    const float* lin_w   = (const float*)d_in[8];
    const float* lin_b   = (const float*)d_in[9];
    const float* diss_w  = (const float*)d_in[10];
    const float* diss_b  = (const float*)d_in[11];
    const float* forc_w  = (const float*)d_in[12];
    const float* forc_b  = (const float*)d_in[13];
    const float* mlp_w1  = (const float*)d_in[14];
    const float* mlp_b1  = (const float*)d_in[15];
    const float* mlp_w2  = (const float*)d_in[16];
    const float* mlp_b2  = (const float*)d_in[17];
    const float* dec_w   = (const float*)d_in[18];
    const float* dec_b   = (const float*)d_in[19];
    float* out = (float*)d_out;

    float *px, *pv;
    cudaGetSymbolAddress((void**)&px, g_x);
    cudaGetSymbolAddress((void**)&pv, g_v);

    const int K1_SMEM  = (2 * 64 * AP + 3 * 64 * BNT) * 4;   // 202752
    const int MLP_SMEM = (4096 + 4096 + 2 * 64 * 68) * 4;
    cudaFuncSetAttribute(k1_kernel,  cudaFuncAttributeMaxDynamicSharedMemorySize, K1_SMEM);
    cudaFuncSetAttribute(mlp_kernel, cudaFuncAttributeMaxDynamicSharedMemorySize, MLP_SMEM);

    const int GB = (NN + 63) / 64;          // 64-node GEMM tiles
    const int NB = (NN + 255) / 256;        // node elementwise (== SB)
    const int WB = (NN + 7) / 8;            // 8 warps (nodes) per 256-thread block
    const int EB = (EE + 255) / 256;        // edge-parallel

    // Dual CSR build (topology fixed across all iterations; self-edges dropped)
    zero_cnt_kernel<<<NB, 256>>>();
    count_kernel<<<EB, 256>>>(ei);
    partial_kernel<<<SB, 256>>>();
    scanpart_kernel<<<1, 512>>>();
    expand_kernel<<<SB, 256>>>();
    scatter_kernel<<<EB, 256>>>(ei);

    // encoder
    gemm_kernel<64><<<GB, 256>>>(x_in, enc_w, enc_b, px, NN);

    for (int blk = 0; blk < 2; ++blk) {
        gemm_kernel<64><<<GB, 256>>>(px, vel_w + blk * 4096, vel_b + blk * 64, pv, NN);
        for (int it = 0; it < 4; ++it) {
            k1_kernel<<<GB, 256, K1_SMEM>>>(lin_w  + blk * 4096, lin_b  + blk * 64,
                                            diss_w + blk * 4096, diss_b + blk * 64,
                                            forc_w + blk * 4096, forc_b + blk * 64,
                                            res_w + blk * 128, res_b + blk);
            deg_kernel<<<WB, 256>>>();
            agg_kernel<<<WB, 256>>>();
        }
        mlp_kernel<<<GB, 256, MLP_SMEM>>>(mlp_w1 + blk * 4096, mlp_b1 + blk * 64,
                                          mlp_w2 + blk * 4096, mlp_b2 + blk * 64);
    }

    // decoder
    gemm_kernel<32><<<GB, 256>>>(px, dec_w, dec_b, out, NN);
}

// round 10
// speedup vs baseline: 2.3882x; 2.3882x over previous
#include <cuda_runtime.h>
#include <cuda_fp16.h>
#include <math.h>

#define NN 100000
#define EE 3200000
#define DD 64
constexpr float EPSF = 0.01f;
#define SB ((NN + 255) / 256)   // 391 scan blocks

// ---------------- scratch (device globals; no allocation allowed) ----------------
__device__ __align__(16) float  g_x [NN * DD];   // node state h
__device__ __align__(16) float  g_v [NN * DD];   // velocity (vp after k1)
__device__ __align__(16) __half g_lxh[NN * DD];  // fp16 lx for the gather
__device__ __align__(16) float  g_a  [NN];
__device__ __align__(16) float  g_b  [NN];       // x@wb + rb
__device__ __align__(16) float2 g_ad [NN];       // (a, dinv)
// CSR by col (for agg) and by row (for deg)
__device__ __align__(16) int g_ccnt [NN];
__device__ __align__(16) int g_cptr [NN + 1];
__device__ __align__(16) int g_cfill[NN];
__device__ __align__(16) int g_src  [EE];        // source node per col-CSR slot
__device__ __align__(16) int g_rcnt [NN];
__device__ __align__(16) int g_rptr [NN + 1];
__device__ __align__(16) int g_rfill[NN];
__device__ __align__(16) int g_rcol [EE];        // dest node per row-CSR slot
__device__ __align__(16) int g_cpart[512];
__device__ __align__(16) int g_rpart[512];

// ---------------- CSR build (self-edges dropped: valid = row!=col) ----------------
__global__ void zero_cnt_kernel() {
    int i = blockIdx.x * blockDim.x + threadIdx.x;
    if (i < NN) { g_ccnt[i] = 0; g_rcnt[i] = 0; }
}

__global__ void count_kernel(const int* __restrict__ ei) {
    int e = blockIdx.x * blockDim.x + threadIdx.x;
    if (e >= EE) return;
    int r = ei[e], c = ei[EE + e];
    if (r == c) return;
    atomicAdd(&g_ccnt[c], 1);
    atomicAdd(&g_rcnt[r], 1);
}

// --- multi-block scan: partial sums -> scan partials -> expand ---
__global__ void partial_kernel() {
    __shared__ int smc[256], smr[256];
    int t = threadIdx.x;
    int i = blockIdx.x * 256 + t;
    int vc = (i < NN) ? g_ccnt[i] : 0;
    int vr = (i < NN) ? g_rcnt[i] : 0;
    smc[t] = vc; smr[t] = vr;
    __syncthreads();
#pragma unroll
    for (int off = 128; off; off >>= 1) {
        if (t < off) { smc[t] += smc[t + off]; smr[t] += smr[t + off]; }
        __syncthreads();
    }
    if (t == 0) { g_cpart[blockIdx.x] = smc[0]; g_rpart[blockIdx.x] = smr[0]; }
}

__global__ void scanpart_kernel() {
    __shared__ int smc[512], smr[512];
    int t = threadIdx.x;
    int vc = (t < SB) ? g_cpart[t] : 0;
    int vr = (t < SB) ? g_rpart[t] : 0;
    smc[t] = vc; smr[t] = vr;
    __syncthreads();
#pragma unroll
    for (int off = 1; off < 512; off <<= 1) {
        int ac = (t >= off) ? smc[t - off] : 0;
        int ar = (t >= off) ? smr[t - off] : 0;
        __syncthreads();
        smc[t] += ac; smr[t] += ar;
        __syncthreads();
    }
    if (t < SB) { g_cpart[t] = smc[t] - vc; g_rpart[t] = smr[t] - vr; }
    if (t == 511) { g_cptr[NN] = smc[511]; g_rptr[NN] = smr[511]; }
}

__global__ void expand_kernel() {
    __shared__ int smc[256], smr[256];
    int b = blockIdx.x, t = threadIdx.x;
    int i = b * 256 + t;
    int vc = (i < NN) ? g_ccnt[i] : 0;
    int vr = (i < NN) ? g_rcnt[i] : 0;
    smc[t] = vc; smr[t] = vr;
    __syncthreads();
#pragma unroll
    for (int off = 1; off < 256; off <<= 1) {
        int ac = (t >= off) ? smc[t - off] : 0;
        int ar = (t >= off) ? smr[t - off] : 0;
        __syncthreads();
        smc[t] += ac; smr[t] += ar;
        __syncthreads();
    }
    if (i < NN) {
        int pc = g_cpart[b] + smc[t] - vc;
        int pr = g_rpart[b] + smr[t] - vr;
        g_cptr[i] = pc; g_cfill[i] = pc;
        g_rptr[i] = pr; g_rfill[i] = pr;
    }
}

__global__ void scatter_kernel(const int* __restrict__ ei) {
    int e = blockIdx.x * blockDim.x + threadIdx.x;
    if (e >= EE) return;
    int r = ei[e], c = ei[EE + e];
    if (r == c) return;
    int sc = atomicAdd(&g_cfill[c], 1);
    g_src[sc] = r;
    int sr = atomicAdd(&g_rfill[r], 1);
    g_rcol[sr] = c;
}

// ---------------- shared helpers ----------------
__device__ __forceinline__ void load_xtile(const float* __restrict__ X, float* Xs,
                                           int node0, int nrows, int tid) {
    // Xs[k][m], pitch 68 floats, 64x64 tile transposed
    for (int i = tid; i < 1024; i += 256) {
        int m = i >> 4, q = i & 15;
        float4 v = make_float4(0.f, 0.f, 0.f, 0.f);
        int node = node0 + m;
        if (node < nrows) v = reinterpret_cast<const float4*>(X)[node * 16 + q];
        int k = q * 4;
        Xs[(k + 0) * 68 + m] = v.x;
        Xs[(k + 1) * 68 + m] = v.y;
        Xs[(k + 2) * 68 + m] = v.z;
        Xs[(k + 3) * 68 + m] = v.w;
    }
}

__device__ __forceinline__ float gelu_tanh(float x) {
    float x3 = x * x * x;
    float t = tanhf(0.7978845608028654f * (x + 0.044715f * x3));
    return 0.5f * x * (1.0f + t);
}

// ---------------- generic GEMM: Y[m][0..BN) = X[m] @ W + bias ----------------
template <int BN>
__global__ void gemm_kernel(const float* __restrict__ X, const float* __restrict__ W,
                            const float* __restrict__ bias, float* __restrict__ Y,
                            int nrows) {
    __shared__ float Ws[64 * BN];
    __shared__ float Xs[64 * 68];
    int tid = threadIdx.x;
    for (int i = tid; i < 64 * BN / 4; i += 256)
        reinterpret_cast<float4*>(Ws)[i] = reinterpret_cast<const float4*>(W)[i];
    int node0 = blockIdx.x * 64;
    load_xtile(X, Xs, node0, nrows, tid);
    __syncthreads();

    constexpr int NT = BN / 16;
    int tm = tid & 15, tn = tid >> 4;
    int m0 = tm * 4;
    float acc[4][NT];
#pragma unroll
    for (int i = 0; i < 4; ++i)
#pragma unroll
        for (int j = 0; j < NT; ++j) acc[i][j] = 0.f;

#pragma unroll 4
    for (int k = 0; k < 64; ++k) {
        float4 xv = *reinterpret_cast<const float4*>(Xs + k * 68 + m0);
        float xr[4] = {xv.x, xv.y, xv.z, xv.w};
        float wr[NT];
#pragma unroll
        for (int j = 0; j < NT; ++j) wr[j] = Ws[k * BN + tn * NT + j];
#pragma unroll
        for (int i = 0; i < 4; ++i)
#pragma unroll
            for (int j = 0; j < NT; ++j) acc[i][j] = fmaf(xr[i], wr[j], acc[i][j]);
    }
    float br[NT];
#pragma unroll
    for (int j = 0; j < NT; ++j) br[j] = bias[tn * NT + j];
#pragma unroll
    for (int i = 0; i < 4; ++i) {
        int m = node0 + m0 + i;
        if (m < nrows) {
#pragma unroll
            for (int j = 0; j < NT; ++j) Y[m * BN + tn * NT + j] = acc[i][j] + br[j];
        }
    }
}

// ---------------- k1: lx/diss/forc GEMMs + a,b dots fused into partial v update ----
// vp = v*(1 - EPS*relu(diss)) - EPS*lx + EPS*forc ; lx stored fp16 for gather;
// a = x@wa, b = x@wb + rb written per node (tn==0 threads).
__global__ void k1_kernel(const float* __restrict__ Wl, const float* __restrict__ bl,
                          const float* __restrict__ Wd, const float* __restrict__ bd,
                          const float* __restrict__ Wf, const float* __restrict__ bf,
                          const float* __restrict__ res_w_blk,
                          const float* __restrict__ res_b_blk) {
    extern __shared__ float sm[];
    float* Ws = sm;              // 64 x 192 (cols: 0-63 lin, 64-127 diss, 128-191 forc)
    float* Xs = sm + 64 * 192;   // 64 x 68
    __shared__ float Wab[128];   // wa[64], wb[64]
    int tid = threadIdx.x;
    for (int i = tid; i < 3072; i += 256) {
        int k = i / 48, q = i % 48;
        const float* src = (q < 16) ? Wl : (q < 32) ? Wd : Wf;
        int qq = q & 15;
        reinterpret_cast<float4*>(Ws + k * 192)[q] =
            reinterpret_cast<const float4*>(src + k * 64)[qq];
    }
    if (tid < 128) Wab[tid] = res_w_blk[tid];
    int node0 = blockIdx.x * 64;
    load_xtile(g_x, Xs, node0, NN, tid);
    __syncthreads();

    int tm = tid & 15, tn = tid >> 4;
    int m0 = tm * 4;
    float acc[4][3][4];
    float a_p[4] = {0.f, 0.f, 0.f, 0.f};
    float b_p[4] = {0.f, 0.f, 0.f, 0.f};
#pragma unroll
    for (int i = 0; i < 4; ++i)
#pragma unroll
        for (int s = 0; s < 3; ++s)
#pragma unroll
            for (int j = 0; j < 4; ++j) acc[i][s][j] = 0.f;

#pragma unroll 4
    for (int k = 0; k < 64; ++k) {
        float4 xv = *reinterpret_cast<const float4*>(Xs + k * 68 + m0);
        float xr[4] = {xv.x, xv.y, xv.z, xv.w};
#pragma unroll
        for (int s = 0; s < 3; ++s) {
            float4 wv = *reinterpret_cast<const float4*>(Ws + k * 192 + s * 64 + tn * 4);
            float wr[4] = {wv.x, wv.y, wv.z, wv.w};
#pragma unroll
            for (int i = 0; i < 4; ++i)
#pragma unroll
                for (int j = 0; j < 4; ++j)
                    acc[i][s][j] = fmaf(xr[i], wr[j], acc[i][s][j]);
        }
        float wa = Wab[k], wb = Wab[64 + k];
#pragma unroll
        for (int i = 0; i < 4; ++i) {
            a_p[i] = fmaf(xr[i], wa, a_p[i]);
            b_p[i] = fmaf(xr[i], wb, b_p[i]);
        }
    }
    float4 b_l = *reinterpret_cast<const float4*>(bl + tn * 4);
    float4 b_d = *reinterpret_cast<const float4*>(bd + tn * 4);
    float4 b_f = *reinterpret_cast<const float4*>(bf + tn * 4);
    float blr[4] = {b_l.x, b_l.y, b_l.z, b_l.w};
    float bdr[4] = {b_d.x, b_d.y, b_d.z, b_d.w};
    float bfr[4] = {b_f.x, b_f.y, b_f.z, b_f.w};
    float rb = res_b_blk[0];
#pragma unroll
    for (int i = 0; i < 4; ++i) {
        int m = node0 + m0 + i;
        if (m < NN) {
            int o = m * 64 + tn * 4;
            float4 v4 = *reinterpret_cast<const float4*>(g_v + o);
            float vr[4] = {v4.x, v4.y, v4.z, v4.w};
            float lx[4], vp[4];
#pragma unroll
            for (int j = 0; j < 4; ++j) {
                lx[j] = acc[i][0][j] + blr[j];
                float ds = fmaxf(acc[i][1][j] + bdr[j], 0.f);
                float fc = acc[i][2][j] + bfr[j];
                vp[j] = vr[j] - EPSF * (lx[j] + ds * vr[j] - fc);
            }
            *reinterpret_cast<float4*>(g_v + o) = make_float4(vp[0], vp[1], vp[2], vp[3]);
            __half2* lh = reinterpret_cast<__half2*>(g_lxh + o);
            lh[0] = __floats2half2_rn(lx[0], lx[1]);
            lh[1] = __floats2half2_rn(lx[2], lx[3]);
            if (tn == 0) {
                g_a[m] = a_p[i];
                g_b[m] = b_p[i] + rb;
            }
        }
    }
}

// ---------------- fused MLP block: h += gelu(h@W1+b1)@W2+b2 ----------------
__global__ void mlp_kernel(const float* __restrict__ W1, const float* __restrict__ b1,
                           const float* __restrict__ W2, const float* __restrict__ b2) {
    extern __shared__ float sm[];
    float* W1s = sm;                 // 4096
    float* W2s = sm + 4096;          // 4096
    float* Xs  = sm + 8192;          // 64*68
    float* Ts  = sm + 8192 + 4352;   // 64*68
    int tid = threadIdx.x;
    for (int i = tid; i < 1024; i += 256) {
        reinterpret_cast<float4*>(W1s)[i] = reinterpret_cast<const float4*>(W1)[i];
        reinterpret_cast<float4*>(W2s)[i] = reinterpret_cast<const float4*>(W2)[i];
    }
    int node0 = blockIdx.x * 64;
    load_xtile(g_x, Xs, node0, NN, tid);
    __syncthreads();

    int tm = tid & 15, tn = tid >> 4;
    int m0 = tm * 4;
    float acc[4][4];
#pragma unroll
    for (int i = 0; i < 4; ++i)
#pragma unroll
        for (int j = 0; j < 4; ++j) acc[i][j] = 0.f;

#pragma unroll 4
    for (int k = 0; k < 64; ++k) {
        float4 xv = *reinterpret_cast<const float4*>(Xs + k * 68 + m0);
        float xr[4] = {xv.x, xv.y, xv.z, xv.w};
        float4 wv = *reinterpret_cast<const float4*>(W1s + k * 64 + tn * 4);
        float wr[4] = {wv.x, wv.y, wv.z, wv.w};
#pragma unroll
        for (int i = 0; i < 4; ++i)
#pragma unroll
            for (int j = 0; j < 4; ++j) acc[i][j] = fmaf(xr[i], wr[j], acc[i][j]);
    }
    float4 bb1 = *reinterpret_cast<const float4*>(b1 + tn * 4);
    float br1[4] = {bb1.x, bb1.y, bb1.z, bb1.w};
#pragma unroll
    for (int i = 0; i < 4; ++i)
#pragma unroll
        for (int j = 0; j < 4; ++j)
            Ts[(tn * 4 + j) * 68 + m0 + i] = gelu_tanh(acc[i][j] + br1[j]);
    __syncthreads();

    float acc2[4][4];
#pragma unroll
    for (int i = 0; i < 4; ++i)
#pragma unroll
        for (int j = 0; j < 4; ++j) acc2[i][j] = 0.f;
#pragma unroll 4
    for (int k = 0; k < 64; ++k) {
        float4 tv = *reinterpret_cast<const float4*>(Ts + k * 68 + m0);
        float tr[4] = {tv.x, tv.y, tv.z, tv.w};
        float4 wv = *reinterpret_cast<const float4*>(W2s + k * 64 + tn * 4);
        float wr[4] = {wv.x, wv.y, wv.z, wv.w};
#pragma unroll
        for (int i = 0; i < 4; ++i)
#pragma unroll
            for (int j = 0; j < 4; ++j) acc2[i][j] = fmaf(tr[i], wr[j], acc2[i][j]);
    }
    float4 bb2 = *reinterpret_cast<const float4*>(b2 + tn * 4);
    float br2[4] = {bb2.x, bb2.y, bb2.z, bb2.w};
#pragma unroll
    for (int i = 0; i < 4; ++i) {
        int m = node0 + m0 + i;
        if (m < NN) {
#pragma unroll
            for (int j = 0; j < 4; ++j) {
                int n = tn * 4 + j;
                g_x[m * 64 + n] = Xs[n * 68 + m0 + i] + acc2[i][j] + br2[j];
            }
        }
    }
}

// ---------------- deg via row-CSR gather (no atomics) + dinv fused ----------------
__global__ void deg_kernel() {
    int warp = (blockIdx.x * blockDim.x + threadIdx.x) >> 5;
    int lane = threadIdx.x & 31;
    if (warp >= NN) return;
    int r = warp;
    int lo = g_rptr[r], hi = g_rptr[r + 1];
    float a_r = __ldg(&g_a[r]);
    float s = 0.f;
#pragma unroll 4
    for (int p = lo + lane; p < hi; p += 32) {
        int c = __ldg(&g_rcol[p]);
        float z = a_r + __ldg(&g_b[c]);
        if (z > 0.f) s += z;
    }
#pragma unroll
    for (int off = 16; off; off >>= 1) s += __shfl_xor_sync(0xFFFFFFFFu, s, off);
    if (lane == 0)
        g_ad[r] = make_float2(a_r, (s > 0.f) ? rsqrtf(s) : 0.f);
}

// ---------------- aggregation + v/x update (warp per destination node) ----------------
// Lane-parallel metadata (32 edges), then 8-wide bit extraction: 8 independent
// 128B lx gathers in flight per inner iteration (MLP=8).
__global__ void agg_kernel() {
    int warp = (blockIdx.x * blockDim.x + threadIdx.x) >> 5;
    int lane = threadIdx.x & 31;
    if (warp >= NN) return;
    int c = warp;
    int p = g_cptr[c], end = g_cptr[c + 1];
    float dc = __ldg(&g_ad[c]).y;
    float bc = __ldg(&g_b[c]);
    float acc0 = 0.f, acc1 = 0.f;
    const __half2* lxh2 = reinterpret_cast<const __half2*>(g_lxh);

    for (int base = p; base < end; base += 32) {
        int e = base + lane;
        int s = 0;
        float w = 0.f;
        if (e < end) {
            s = __ldg(&g_src[e]);
            float2 ads = __ldg(&g_ad[s]);
            float z = ads.x + bc;
            w = (z > 0.f) ? z * ads.y : 0.f;
        }
        unsigned mask = __ballot_sync(0xFFFFFFFFu, w > 0.f);
        while (mask) {
            int bb[8];
            bool vv_[8];
            bb[0] = __ffs(mask) - 1; mask &= mask - 1; vv_[0] = true;
#pragma unroll
            for (int q = 1; q < 8; ++q) {
                if (mask) { bb[q] = __ffs(mask) - 1; mask &= mask - 1; vv_[q] = true; }
                else      { bb[q] = bb[0]; vv_[q] = false; }
            }
            float wq[8]; int sq[8];
#pragma unroll
            for (int q = 0; q < 8; ++q) {
                wq[q] = __shfl_sync(0xFFFFFFFFu, w, bb[q]);
                sq[q] = __shfl_sync(0xFFFFFFFFu, s, bb[q]);
            }
#pragma unroll
            for (int q = 1; q < 8; ++q) if (!vv_[q]) wq[q] = 0.f;
            __half2 hq[8];
#pragma unroll
            for (int q = 0; q < 8; ++q) hq[q] = __ldg(lxh2 + sq[q] * 32 + lane);
#pragma unroll
            for (int q = 0; q < 8; ++q) {
                float2 lf = __half22float2(hq[q]);
                acc0 = fmaf(wq[q], lf.x, acc0);
                acc1 = fmaf(wq[q], lf.y, acc1);
            }
        }
    }
    int idx = c * 32 + lane;
    float2 vv = reinterpret_cast<float2*>(g_v)[idx];   // vp from k1
    float2 xx = reinterpret_cast<float2*>(g_x)[idx];
    vv.x += EPSF * dc * acc0;
    vv.y += EPSF * dc * acc1;
    xx.x += EPSF * vv.x;
    xx.y += EPSF * vv.y;
    reinterpret_cast<float2*>(g_v)[idx] = vv;
    reinterpret_cast<float2*>(g_x)[idx] = xx;
}

// ---------------- host launch ----------------
extern "C" void kernel_launch(void* const* d_in, const int* in_sizes, int n_in,
                              void* d_out, int out_size) {
    const float* x_in    = (const float*)d_in[0];
    const int*   ei      = (const int*)  d_in[1];
    const float* enc_w   = (const float*)d_in[2];
    const float* enc_b   = (const float*)d_in[3];
    const float* vel_w   = (const float*)d_in[4];
    const float* vel_b   = (const float*)d_in[5];
    const float* res_w   = (const float*)d_in[6];
    const float* res_b   = (const float*)d_in[7];
    const float* lin_w   = (const float*)d_in[8];
    const float* lin_b   = (const float*)d_in[9];
    const float* diss_w  = (const float*)d_in[10];
    const float* diss_b  = (const float*)d_in[11];
    const float* forc_w  = (const float*)d_in[12];
    const float* forc_b  = (const float*)d_in[13];
    const float* mlp_w1  = (const float*)d_in[14];
    const float* mlp_b1  = (const float*)d_in[15];
    const float* mlp_w2  = (const float*)d_in[16];
    const float* mlp_b2  = (const float*)d_in[17];
    const float* dec_w   = (const float*)d_in[18];
    const float* dec_b   = (const float*)d_in[19];
    float* out = (float*)d_out;

    float *px, *pv;
    cudaGetSymbolAddress((void**)&px, g_x);
    cudaGetSymbolAddress((void**)&pv, g_v);

    const int K1_SMEM  = (192 * 64 + 64 * 68) * 4;
    const int MLP_SMEM = (4096 + 4096 + 2 * 64 * 68) * 4;
    cudaFuncSetAttribute(k1_kernel,  cudaFuncAttributeMaxDynamicSharedMemorySize, K1_SMEM);
    cudaFuncSetAttribute(mlp_kernel, cudaFuncAttributeMaxDynamicSharedMemorySize, MLP_SMEM);

    const int GB = (NN + 63) / 64;          // 64-node GEMM tiles
    const int NB = (NN + 255) / 256;        // node elementwise (== SB)
    const int WB = (NN + 7) / 8;            // 8 warps (nodes) per 256-thread block
    const int EB = (EE + 255) / 256;        // edge-parallel

    // Dual CSR build (topology fixed across all iterations; self-edges dropped)
    zero_cnt_kernel<<<NB, 256>>>();
    count_kernel<<<EB, 256>>>(ei);
    partial_kernel<<<SB, 256>>>();
    scanpart_kernel<<<1, 512>>>();
    expand_kernel<<<SB, 256>>>();
    scatter_kernel<<<EB, 256>>>(ei);

    // encoder
    gemm_kernel<64><<<GB, 256>>>(x_in, enc_w, enc_b, px, NN);

    for (int blk = 0; blk < 2; ++blk) {
        gemm_kernel<64><<<GB, 256>>>(px, vel_w + blk * 4096, vel_b + blk * 64, pv, NN);
        for (int it = 0; it < 4; ++it) {
            k1_kernel<<<GB, 256, K1_SMEM>>>(lin_w  + blk * 4096, lin_b  + blk * 64,
                                            diss_w + blk * 4096, diss_b + blk * 64,
                                            forc_w + blk * 4096, forc_b + blk * 64,
                                            res_w + blk * 128, res_b + blk);
            deg_kernel<<<WB, 256>>>();
            agg_kernel<<<WB, 256>>>();
        }
        mlp_kernel<<<GB, 256, MLP_SMEM>>>(mlp_w1 + blk * 4096, mlp_b1 + blk * 64,
                                          mlp_w2 + blk * 4096, mlp_b2 + blk * 64);
    }

    // decoder
    gemm_kernel<32><<<GB, 256>>>(px, dec_w, dec_b, out, NN);
}